// round 2
// baseline (speedup 1.0000x reference)
#include <cuda_runtime.h>
#include <cstdint>

#define NB   148          // one wave on 148-SM sm_100a
#define NT   512
#define NMAX 8192
#define EPT  (NMAX / NT)  // 16 elements per thread for compaction

// ---- Blackwell packed f32x2 helpers ----
#define PACKF2(r, lo, hi)  asm("mov.b64 %0, {%1, %2};" : "=l"(r) : "f"(lo), "f"(hi))
#define UNPACKF2(lo, hi, x) asm("mov.b64 {%0, %1}, %2;" : "=f"(lo), "=f"(hi) : "l"(x))
#define ADDF2(r, a, b) asm("add.rn.f32x2 %0, %1, %2;" : "=l"(r) : "l"(a), "l"(b))
#define MULF2(r, a, b) asm("mul.rn.f32x2 %0, %1, %2;" : "=l"(r) : "l"(a), "l"(b))

// Dynamic smem layout:
//   [0, 65536)        : packed column data. Pair k (cols 2k,2k+1) is a ulonglong2:
//                       .x = {-p[2k], -p[2k+1]}  .y = {-t[2k], -t[2k+1]}
//   [65536, 65600)    : float red[16]
//   [65600, 65664)    : int   iscan[16]
#define SMEM_BYTES (65536 + 64 + 64)

__global__ __launch_bounds__(NT, 1)
void cindex_kernel(const float* __restrict__ pred,
                   const float* __restrict__ gt,
                   const int* __restrict__ ft_idx,
                   const int* __restrict__ fm_idx,
                   float* __restrict__ out, int n)
{
    extern __shared__ unsigned char smem_raw[];
    float*            fview = (float*)smem_raw;
    const ulonglong2* cview = (const ulonglong2*)smem_raw;
    float* red  = (float*)(smem_raw + 65536);
    int*   iscn = (int*)(smem_raw + 65536 + 64);
    __shared__ int s_m;

    const int tid  = threadIdx.x;
    const int lane = tid & 31;
    const int wid  = tid >> 5;
    const int fm   = fm_idx[0];
    const int ft   = ft_idx[0];

    // ---- Phase A: per-thread flag counts over contiguous chunk [tid*EPT, +EPT) ----
    unsigned int flagmask = 0;
    int cnt = 0;
    const int e0 = tid * EPT;
    #pragma unroll
    for (int q = 0; q < EPT; ++q) {
        int e = e0 + q;
        float w = (e < n) ? gt[e * 2 + fm] : 0.0f;
        if (w == 1.0f) { flagmask |= 1u << q; cnt++; }
    }

    // ---- Phase B: block-wide exclusive scan of counts (order-preserving, deterministic) ----
    int incl = cnt;
    #pragma unroll
    for (int o = 1; o < 32; o <<= 1) {
        int v = __shfl_up_sync(0xffffffffu, incl, o);
        if (lane >= o) incl += v;
    }
    if (lane == 31) iscn[wid] = incl;
    __syncthreads();
    if (wid == 0) {
        int v = (lane < 16) ? iscn[lane] : 0;
        #pragma unroll
        for (int o = 1; o < 16; o <<= 1) {
            int u = __shfl_up_sync(0xffffffffu, v, o);
            if (lane >= o) v += u;
        }
        if (lane < 16) iscn[lane] = v;     // inclusive warp totals
        if (lane == 15) s_m = v;           // total flagged count m
    }
    __syncthreads();
    const int m = s_m;
    int idx = (wid ? iscn[wid - 1] : 0) + (incl - cnt);  // exclusive thread base
    __syncthreads();  // iscn no longer needed; fview writes next

    // ---- Phase C: write compacted, negated columns into smem ----
    #pragma unroll
    for (int q = 0; q < EPT; ++q) {
        if (flagmask & (1u << q)) {
            int e = e0 + q;
            fview[(idx >> 1) * 4 +     (idx & 1)] = -pred[e];
            fview[(idx >> 1) * 4 + 2 + (idx & 1)] = -gt[e * 2 + ft];
            idx++;
        }
    }
    __syncthreads();

    // ---- Phase D: pair loop. flat = s*m + i  (warps share slice s -> broadcast LDS) ----
    float v = 0.0f;
    const long long Ttot = (long long)NB * NT;
    if (m > 1) {
        const int S = (int)(Ttot / m);       // column slices (>= 9 for m <= 8192)
        const long long flat = (long long)blockIdx.x * NT + tid;
        if (flat < (long long)S * m) {
            const int s = (int)(flat / m);
            const int i = (int)(flat % m);
            const float pi = -fview[(i >> 1) * 4 +     (i & 1)];
            const float ti = -fview[(i >> 1) * 4 + 2 + (i & 1)];
            uint64_t pi2, ti2;
            PACKF2(pi2, pi, pi);
            PACKF2(ti2, ti, ti);

            const int c0 = (int)((long long)s * m / S);
            const int c1 = (int)((long long)(s + 1) * m / S);

            uint64_t sx0 = 0, sa0 = 0, sx1 = 0, sa1 = 0;
            float rs = 0.0f;  // scalar relu sum (head/tail)

            int j = c0;
            if (j & 1) {   // odd head
                float dp = pi + fview[(j >> 1) * 4 +     (j & 1)];
                float dt = ti + fview[(j >> 1) * 4 + 2 + (j & 1)];
                rs += fmaxf(dp * dt, 0.0f);
                j++;
            }
            const int jend = c1 & ~1;
            // two independent accumulator chains
            for (; j + 3 < jend; j += 4) {
                ulonglong2 va = cview[(j >> 1)];
                ulonglong2 vb = cview[(j >> 1) + 1];
                uint64_t dp2, dt2, x2, a2;
                ADDF2(dp2, pi2, va.x);
                ADDF2(dt2, ti2, va.y);
                MULF2(x2, dp2, dt2);
                ADDF2(sx0, sx0, x2);
                a2 = x2 & 0x7fffffff7fffffffULL;
                ADDF2(sa0, sa0, a2);
                ADDF2(dp2, pi2, vb.x);
                ADDF2(dt2, ti2, vb.y);
                MULF2(x2, dp2, dt2);
                ADDF2(sx1, sx1, x2);
                a2 = x2 & 0x7fffffff7fffffffULL;
                ADDF2(sa1, sa1, a2);
            }
            for (; j + 1 < c1 + 1 && j + 1 < jend + 1 && j < jend; j += 2) {
                ulonglong2 va = cview[(j >> 1)];
                uint64_t dp2, dt2, x2, a2;
                ADDF2(dp2, pi2, va.x);
                ADDF2(dt2, ti2, va.y);
                MULF2(x2, dp2, dt2);
                ADDF2(sx0, sx0, x2);
                a2 = x2 & 0x7fffffff7fffffffULL;
                ADDF2(sa0, sa0, a2);
            }
            if (j < c1) {  // odd tail
                float dp = pi + fview[(j >> 1) * 4 +     (j & 1)];
                float dt = ti + fview[(j >> 1) * 4 + 2 + (j & 1)];
                rs += fmaxf(dp * dt, 0.0f);
            }

            uint64_t sxT, saT;
            ADDF2(sxT, sx0, sx1);
            ADDF2(saT, sa0, sa1);
            float xl, xh, al, ah;
            UNPACKF2(xl, xh, sxT);
            UNPACKF2(al, ah, saT);
            // relu sum = 0.5*(sum_x + sum_|x|)  (+ scalar head/tail relus)
            v = 0.5f * ((xl + xh) + (al + ah)) + rs;
        }
    }

    // ---- Phase E: block reduce, pre-scaled atomic into out ----
    #pragma unroll
    for (int o = 16; o > 0; o >>= 1) v += __shfl_down_sync(0xffffffffu, v, o);
    if (lane == 0) red[wid] = v;
    __syncthreads();
    if (wid == 0) {
        float t = (lane < 16) ? red[lane] : 0.0f;
        #pragma unroll
        for (int o = 8; o > 0; o >>= 1) t += __shfl_down_sync(0xffffffffu, t, o);
        if (lane == 0 && m > 1) {
            // full ordered-pair sum F: answer = F / (100*m*(m-1))
            double sc = 1.0 / (100.0 * (double)m * ((double)m - 1.0));
            atomicAdd(out, (float)((double)t * sc));
        }
    }
}

extern "C" void kernel_launch(void* const* d_in, const int* in_sizes, int n_in,
                              void* d_out, int out_size) {
    const float* pred = (const float*)d_in[0];
    const float* gt   = (const float*)d_in[1];
    const int* ft     = (const int*)d_in[2];
    const int* fm     = (const int*)d_in[3];
    float* out        = (float*)d_out;
    const int n = in_sizes[0];

    cudaFuncSetAttribute(cindex_kernel,
                         cudaFuncAttributeMaxDynamicSharedMemorySize, SMEM_BYTES);
    cudaMemsetAsync(out, 0, sizeof(float));
    cindex_kernel<<<NB, NT, SMEM_BYTES>>>(pred, gt, ft, fm, out, n);
}

// round 4
// speedup vs baseline: 1.3536x; 1.3536x over previous
#include <cuda_runtime.h>
#include <cstdint>

#define NB   148
#define NT   512
#define TOT  (NB * NT)

// ---- Blackwell packed f32x2 helpers ----
#define PACKF2(r, lo, hi)   asm("mov.b64 %0, {%1, %2};" : "=l"(r) : "f"(lo), "f"(hi))
#define UNPACKF2(lo, hi, x) asm("mov.b64 {%0, %1}, %2;" : "=f"(lo), "=f"(hi) : "l"(x))
#define ADDF2(r, a, b) asm("add.rn.f32x2 %0, %1, %2;" : "=l"(r) : "l"(a), "l"(b))
#define MULF2(r, a, b) asm("mul.rn.f32x2 %0, %1, %2;" : "=l"(r) : "l"(a), "l"(b))

// dynamic smem:
//   [0,      65536) : float2 stage[8192]  (negated raw rows, uncompacted)
//   [65536, 131072) : packed compacted columns; pair k at 16B:
//                     { -p[2k], -p[2k+1], -t[2k], -t[2k+1] }
#define STAGE_OFF 0
#define COL_OFF   65536
#define SMEM_BYTES 131072

__device__ unsigned long long g_acc  = 0ULL;  // fixed-point sum, scale 2^16 (two's complement)
__device__ unsigned int       g_done = 0;

__global__ __launch_bounds__(NT, 1)
void cindex_kernel(const float* __restrict__ pred,
                   const float* __restrict__ gt,
                   const int* __restrict__ ft_idx,
                   const int* __restrict__ fm_idx,
                   float* __restrict__ out, int n)
{
    extern __shared__ unsigned char smem_raw[];
    float2*           stage = (float2*)(smem_raw + STAGE_OFF);
    float*            fview = (float*)(smem_raw + COL_OFF);
    const ulonglong2* cview = (const ulonglong2*)(smem_raw + COL_OFF);
    __shared__ int   iscn[NT / 32];
    __shared__ int   s_m;
    __shared__ float red[NT / 32];

    const int tid  = threadIdx.x;
    const int lane = tid & 31;
    const int wid  = tid >> 5;
    const int fm   = fm_idx[0];
    const int ft   = ft_idx[0];

    // ---- Phase A1: coalesced load + stage + flag count (deterministic) ----
    const int iters = (n + NT - 1) / NT;
    unsigned flags = 0;
    int cnt = 0;
    for (int q = 0; q < iters; ++q) {
        const int e = q * NT + tid;
        if (e < n) {
            float w = gt[e * 2 + fm];
            stage[e] = make_float2(-pred[e], -gt[e * 2 + ft]);
            if (w == 1.0f) { flags |= 1u << q; cnt++; }
        }
    }

    // ---- Phase A2: block scan of cnt in tid order (deterministic ranks) ----
    int incl = cnt;
    #pragma unroll
    for (int o = 1; o < 32; o <<= 1) {
        int v = __shfl_up_sync(0xffffffffu, incl, o);
        if (lane >= o) incl += v;
    }
    if (lane == 31) iscn[wid] = incl;
    __syncthreads();
    if (wid == 0) {
        int v = (lane < NT / 32) ? iscn[lane] : 0;
        #pragma unroll
        for (int o = 1; o < NT / 32; o <<= 1) {
            int u = __shfl_up_sync(0xffffffffu, v, o);
            if (lane >= o) v += u;
        }
        if (lane < NT / 32) iscn[lane] = v;
        if (lane == NT / 32 - 1) s_m = v;
    }
    __syncthreads();
    const int m = s_m;
    int idx = (wid ? iscn[wid - 1] : 0) + (incl - cnt);

    // ---- Phase A3: deterministic compacted scatter from smem staging ----
    for (int q = 0; q < iters; ++q) {
        if (flags & (1u << q)) {
            float2 v = stage[q * NT + tid];
            fview[(idx >> 1) * 4 +     (idx & 1)] = v.x;
            fview[(idx >> 1) * 4 + 2 + (idx & 1)] = v.y;
            idx++;
        }
    }
    // zero-pad odd column so every pair is fully defined
    if (tid == 0 && (m & 1)) {
        fview[(m >> 1) * 4 +     (m & 1)] = 0.0f;
        fview[(m >> 1) * 4 + 2 + (m & 1)] = 0.0f;
    }
    __syncthreads();

    // ---- Phase B: pair loop, 4 rows/thread, packed f32x2 ----
    float v = 0.0f;
    if (m > 1) {
        const int RG = (m + 3) >> 2;          // row groups of 4
        const int S  = TOT / RG;              // column slices (>= 37)
        const int u  = blockIdx.x * NT + tid;
        if (u < S * RG) {
            const int s = u / RG;
            const int g = u % RG;

            float pi_s[4], ti_s[4];
            uint64_t pi2[4], ti2[4], sx[4], sa[4];
            #pragma unroll
            for (int r = 0; r < 4; ++r) {
                int ic = min(4 * g + r, m - 1);       // clamp; masked below
                pi_s[r] = -fview[(ic >> 1) * 4 +     (ic & 1)];
                ti_s[r] = -fview[(ic >> 1) * 4 + 2 + (ic & 1)];
                PACKF2(pi2[r], pi_s[r], pi_s[r]);
                PACKF2(ti2[r], ti_s[r], ti_s[r]);
                sx[r] = 0; sa[r] = 0;
            }

            const int P = (m + 1) >> 1;               // column pairs (incl. pad)
            const int a = (int)((long long)s * P / S);
            const int b = (int)((long long)(s + 1) * P / S);

            #pragma unroll 2
            for (int k = a; k < b; ++k) {
                ulonglong2 va = cview[k];             // broadcast LDS.128
                #pragma unroll
                for (int r = 0; r < 4; ++r) {
                    uint64_t dp2, dt2, x2, a2;
                    ADDF2(dp2, pi2[r], va.x);
                    ADDF2(dt2, ti2[r], va.y);
                    MULF2(x2, dp2, dt2);
                    ADDF2(sx[r], sx[r], x2);
                    a2 = x2 & 0x7fffffff7fffffffULL;
                    ADDF2(sa[r], sa[r], a2);
                }
            }

            // pad column correction: the slice containing pair P-1 included a
            // (0,0) column contributing exactly relu(pi*ti) per row. Remove it.
            const bool haspad = (m & 1) && (b == P) && (b > a);
            #pragma unroll
            for (int r = 0; r < 4; ++r) {
                if (4 * g + r < m) {
                    float xl, xh, al, ah;
                    UNPACKF2(xl, xh, sx[r]);
                    UNPACKF2(al, ah, sa[r]);
                    float vr = 0.5f * ((xl + xh) + (al + ah));
                    if (haspad) vr -= fmaxf(pi_s[r] * ti_s[r], 0.0f);
                    v += vr;
                }
            }
        }
    }

    // ---- Phase C: block reduce -> fixed-point global (order-free exact sum) ----
    #pragma unroll
    for (int o = 16; o > 0; o >>= 1) v += __shfl_down_sync(0xffffffffu, v, o);
    if (lane == 0) red[wid] = v;
    __syncthreads();
    if (wid == 0) {
        float t = (lane < NT / 32) ? red[lane] : 0.0f;
        #pragma unroll
        for (int o = 8; o > 0; o >>= 1) t += __shfl_down_sync(0xffffffffu, t, o);
        if (lane == 0) {
            long long q = llrint((double)t * 65536.0);
            atomicAdd(&g_acc, (unsigned long long)q);
            __threadfence();
            unsigned r = atomicAdd(&g_done, 1u);
            if (r == (unsigned)(gridDim.x - 1)) {      // last block finalizes
                long long total = (long long)g_acc;
                double F = (double)total / 65536.0;    // full ordered-pair sum
                float res = 0.0f;
                if (m > 1)
                    res = (float)(F / (100.0 * (double)m * ((double)m - 1.0)));
                out[0] = res;
                g_acc = 0ULL;                          // self-clean for next call
                g_done = 0u;
            }
        }
    }
}

extern "C" void kernel_launch(void* const* d_in, const int* in_sizes, int n_in,
                              void* d_out, int out_size) {
    const float* pred = (const float*)d_in[0];
    const float* gt   = (const float*)d_in[1];
    const int* ft     = (const int*)d_in[2];
    const int* fm     = (const int*)d_in[3];
    float* out        = (float*)d_out;
    const int n = in_sizes[0];

    cudaFuncSetAttribute(cindex_kernel,
                         cudaFuncAttributeMaxDynamicSharedMemorySize, SMEM_BYTES);
    cindex_kernel<<<NB, NT, SMEM_BYTES>>>(pred, gt, ft, fm, out, n);
}

// round 5
// speedup vs baseline: 1.4200x; 1.0491x over previous
#include <cuda_runtime.h>
#include <cstdint>

#define NB    148
#define NT    768
#define NWARP (NT / 32)
#define UTOT  (NB * NT)
#define MAXQ  11          // ceil(8192 / NT)

// ---- Blackwell packed f32x2 helpers ----
#define PACKF2(r, lo, hi)   asm("mov.b64 %0, {%1, %2};" : "=l"(r) : "f"(lo), "f"(hi))
#define UNPACKF2(lo, hi, x) asm("mov.b64 {%0, %1}, %2;" : "=f"(lo), "=f"(hi) : "l"(x))
#define ADDF2(r, a, b) asm("add.rn.f32x2 %0, %1, %2;" : "=l"(r) : "l"(a), "l"(b))
#define MULF2(r, a, b) asm("mul.rn.f32x2 %0, %1, %2;" : "=l"(r) : "l"(a), "l"(b))

// dynamic smem: 64KB packed compacted columns; pair k at 16B:
//   { -p[2k], -p[2k+1], -t[2k], -t[2k+1] }
#define SMEM_BYTES 65536

__device__ unsigned long long g_acc  = 0ULL;  // fixed-point sum (2^16), two's complement
__device__ unsigned int       g_done = 0;

__global__ __launch_bounds__(NT, 1)
void cindex_kernel(const float* __restrict__ pred,
                   const float* __restrict__ gt,
                   const int* __restrict__ ft_idx,
                   const int* __restrict__ fm_idx,
                   float* __restrict__ out, int n)
{
    extern __shared__ unsigned char smem_raw[];
    float*            fview = (float*)smem_raw;
    const ulonglong2* cview = (const ulonglong2*)smem_raw;
    __shared__ int   iscn[NWARP];
    __shared__ int   s_m;
    __shared__ float red[NWARP];

    const int tid  = threadIdx.x;
    const int lane = tid & 31;
    const int wid  = tid >> 5;
    const int fm   = fm_idx[0];
    const int ft   = ft_idx[0];

    // ---- Phase A1: coalesced load into REGISTERS + flag count (deterministic) ----
    float rp[MAXQ], rt[MAXQ];
    unsigned flags = 0;
    int cnt = 0;
    #pragma unroll
    for (int q = 0; q < MAXQ; ++q) {
        const int e = q * NT + tid;
        if (e < n) {
            float2 gg = ((const float2*)gt)[e];      // one LDG.64 for both cols
            float w  = fm ? gg.y : gg.x;
            float tv = ft ? gg.y : gg.x;
            rp[q] = -pred[e];
            rt[q] = -tv;
            if (w == 1.0f) { flags |= 1u << q; cnt++; }
        }
    }

    // ---- Phase A2: block scan of cnt in tid order (deterministic ranks) ----
    int incl = cnt;
    #pragma unroll
    for (int o = 1; o < 32; o <<= 1) {
        int v = __shfl_up_sync(0xffffffffu, incl, o);
        if (lane >= o) incl += v;
    }
    if (lane == 31) iscn[wid] = incl;
    __syncthreads();
    if (wid == 0) {
        int v = (lane < NWARP) ? iscn[lane] : 0;
        #pragma unroll
        for (int o = 1; o < 32; o <<= 1) {
            int u2 = __shfl_up_sync(0xffffffffu, v, o);
            if (lane >= o) v += u2;
        }
        if (lane < NWARP) iscn[lane] = v;
        if (lane == NWARP - 1) s_m = v;
    }
    __syncthreads();
    const int m = s_m;
    int idx = (wid ? iscn[wid - 1] : 0) + (incl - cnt);

    // ---- Phase A3: deterministic compacted scatter from registers ----
    #pragma unroll
    for (int q = 0; q < MAXQ; ++q) {
        if (flags & (1u << q)) {
            fview[(idx >> 1) * 4 +     (idx & 1)] = rp[q];
            fview[(idx >> 1) * 4 + 2 + (idx & 1)] = rt[q];
            idx++;
        }
    }
    if (tid == 0 && (m & 1)) {   // zero-pad odd column
        fview[(m >> 1) * 4 +     1] = 0.0f;
        fview[(m >> 1) * 4 + 2 + 1] = 0.0f;
    }
    __syncthreads();

    // ---- Phase B: TRIANGLE pair loop. Row-group g (rows 4g..4g+3) owns
    //      column-pairs k in [2g, P).  Work flattened & split evenly. ----
    float v = 0.0f;
    if (m > 1) {
        const int P  = (m + 1) >> 1;          // column pairs (incl. pad)
        const int RG = (m + 3) >> 2;          // row groups
        const long long W = (long long)RG * (P - RG + 1);   // C(RG)
        const int u = blockIdx.x * NT + tid;
        long long w0 = (long long)u * W / UTOT;
        long long w1 = (long long)(u + 1) * W / UTOT;

        // find largest g with C(g) = g*(P-g+1) <= w0
        int g;
        {
            double Pd = (double)(P + 1);
            double disc = Pd * Pd - 4.0 * (double)w0;
            g = (int)((Pd - sqrt(disc)) * 0.5);
            if (g < 0) g = 0;
            if (g > RG - 1) g = RG - 1;
            while (g < RG - 1 && (long long)(g + 1) * (P - g) <= w0) g++;
            while (g > 0 && (long long)g * (P - g + 1) > w0) g--;
        }
        long long w = w0;
        long long cdone = (long long)g * (P - g + 1);

        while (w < w1) {
            const int k0  = 2 * g + (int)(w - cdone);
            long long rem = (long long)(P - k0);
            const int cn  = (int)((w1 - w < rem) ? (w1 - w) : rem);

            float ps[4], ts[4];
            uint64_t pi2[4], ti2[4], sx[4], sa[4];
            #pragma unroll
            for (int r = 0; r < 4; ++r) {
                int ic = min(4 * g + r, m - 1);           // clamp; masked below
                ps[r] = -fview[(ic >> 1) * 4 +     (ic & 1)];
                ts[r] = -fview[(ic >> 1) * 4 + 2 + (ic & 1)];
                PACKF2(pi2[r], ps[r], ps[r]);
                PACKF2(ti2[r], ts[r], ts[r]);
                sx[r] = 0; sa[r] = 0;
            }

            const int kend = k0 + cn;
            #pragma unroll 2
            for (int k = k0; k < kend; ++k) {
                ulonglong2 va = cview[k];                 // LDS.128
                #pragma unroll
                for (int r = 0; r < 4; ++r) {
                    uint64_t dp2, dt2, x2, a2;
                    ADDF2(dp2, pi2[r], va.x);
                    ADDF2(dt2, ti2[r], va.y);
                    MULF2(x2, dp2, dt2);
                    ADDF2(sx[r], sx[r], x2);
                    a2 = x2 & 0x7fffffff7fffffffULL;
                    ADDF2(sa[r], sa[r], a2);
                }
            }

            #pragma unroll
            for (int r = 0; r < 4; ++r) {
                if (4 * g + r < m) {
                    float xl, xh, al, ah;
                    UNPACKF2(xl, xh, sx[r]);
                    UNPACKF2(al, ah, sa[r]);
                    v += 0.5f * ((xl + xh) + (al + ah));  // sum relu = (Σx + Σ|x|)/2
                }
            }
            w += cn;
            cdone += P - 2 * g;
            ++g;
        }

        // ---- Corrections: thread u < RG fixes group u.
        //  * within-group pairs were counted twice -> subtract once each
        //  * odd-m pad column added relu(p_i*t_i) once per row -> subtract
        if (u < RG) {
            const int gg = u;
            const int nv = min(4, m - 4 * gg);
            float ps[4], ts[4];
            for (int r = 0; r < nv; ++r) {
                int ic = 4 * gg + r;
                ps[r] = -fview[(ic >> 1) * 4 +     (ic & 1)];
                ts[r] = -fview[(ic >> 1) * 4 + 2 + (ic & 1)];
            }
            float corr = 0.0f;
            for (int r = 0; r < nv; ++r) {
                for (int s2 = r + 1; s2 < nv; ++s2)
                    corr += fmaxf((ps[r] - ps[s2]) * (ts[r] - ts[s2]), 0.0f);
                if (m & 1)
                    corr += fmaxf(ps[r] * ts[r], 0.0f);
            }
            v -= corr;
        }
    }

    // ---- Phase C: block reduce -> fixed-point global (order-free exact sum) ----
    #pragma unroll
    for (int o = 16; o > 0; o >>= 1) v += __shfl_down_sync(0xffffffffu, v, o);
    if (lane == 0) red[wid] = v;
    __syncthreads();
    if (wid == 0) {
        float t = (lane < NWARP) ? red[lane] : 0.0f;
        #pragma unroll
        for (int o = 16; o > 0; o >>= 1) t += __shfl_down_sync(0xffffffffu, t, o);
        if (lane == 0) {
            long long q = llrint((double)t * 65536.0);
            atomicAdd(&g_acc, (unsigned long long)q);
            __threadfence();
            unsigned r = atomicAdd(&g_done, 1u);
            if (r == (unsigned)(gridDim.x - 1)) {
                long long total = (long long)g_acc;
                double Usum = (double)total / 65536.0;   // unordered-pair relu sum
                float res = 0.0f;
                if (m > 1)
                    res = (float)(Usum / (50.0 * (double)m * ((double)m - 1.0)));
                out[0] = res;
                g_acc = 0ULL;
                g_done = 0u;
            }
        }
    }
}

extern "C" void kernel_launch(void* const* d_in, const int* in_sizes, int n_in,
                              void* d_out, int out_size) {
    const float* pred = (const float*)d_in[0];
    const float* gt   = (const float*)d_in[1];
    const int* ft     = (const int*)d_in[2];
    const int* fm     = (const int*)d_in[3];
    float* out        = (float*)d_out;
    const int n = in_sizes[0];

    cudaFuncSetAttribute(cindex_kernel,
                         cudaFuncAttributeMaxDynamicSharedMemorySize, SMEM_BYTES);
    cindex_kernel<<<NB, NT, SMEM_BYTES>>>(pred, gt, ft, fm, out, n);
}

// round 6
// speedup vs baseline: 1.7433x; 1.2277x over previous
#include <cuda_runtime.h>
#include <cstdint>

#define NB    148
#define NT    768
#define NWARP (NT / 32)
#define NWT   (NB * NWARP)      // 3552 warps total
#define MAXQ  11                // ceil(8192 / NT)

// ---- Blackwell packed f32x2 helpers ----
#define PACKF2(r, lo, hi)   asm("mov.b64 %0, {%1, %2};" : "=l"(r) : "f"(lo), "f"(hi))
#define UNPACKF2(lo, hi, x) asm("mov.b64 {%0, %1}, %2;" : "=f"(lo), "=f"(hi) : "l"(x))
#define ADDF2(r, a, b) asm("add.rn.f32x2 %0, %1, %2;" : "=l"(r) : "l"(a), "l"(b))
#define MULF2(r, a, b) asm("mul.rn.f32x2 %0, %1, %2;" : "=l"(r) : "l"(a), "l"(b))

// dynamic smem: 64KB packed compacted columns; pair k at 16B:
//   { -p[2k], -p[2k+1], -t[2k], -t[2k+1] }
#define SMEM_BYTES 65536

__device__ unsigned long long g_acc  = 0ULL;  // fixed-point (2^16), two's complement
__device__ unsigned int       g_done = 0;

__global__ __launch_bounds__(NT, 1)
void cindex_kernel(const float* __restrict__ pred,
                   const float* __restrict__ gt,
                   const int* __restrict__ ft_idx,
                   const int* __restrict__ fm_idx,
                   float* __restrict__ out, int n)
{
    extern __shared__ unsigned char smem_raw[];
    float*            fview = (float*)smem_raw;
    const ulonglong2* cview = (const ulonglong2*)smem_raw;
    __shared__ int   iscn[NWARP];
    __shared__ int   s_m;
    __shared__ float red[NWARP];

    const int tid  = threadIdx.x;
    const int lane = tid & 31;
    const int wid  = tid >> 5;
    const int fmi  = fm_idx[0];
    const int fti  = ft_idx[0];

    // ---- Phase A1: coalesced load into registers + flag count ----
    float rp[MAXQ], rt[MAXQ];
    unsigned flags = 0;
    int cnt = 0;
    #pragma unroll
    for (int q = 0; q < MAXQ; ++q) {
        const int e = q * NT + tid;
        if (e < n) {
            float2 gg = ((const float2*)gt)[e];
            float w  = fmi ? gg.y : gg.x;
            float tv = fti ? gg.y : gg.x;
            rp[q] = -pred[e];
            rt[q] = -tv;
            if (w == 1.0f) { flags |= 1u << q; cnt++; }
        }
    }

    // ---- Phase A2: deterministic block scan of counts ----
    int incl = cnt;
    #pragma unroll
    for (int o = 1; o < 32; o <<= 1) {
        int v = __shfl_up_sync(0xffffffffu, incl, o);
        if (lane >= o) incl += v;
    }
    if (lane == 31) iscn[wid] = incl;
    __syncthreads();
    if (wid == 0) {
        int v = (lane < NWARP) ? iscn[lane] : 0;
        #pragma unroll
        for (int o = 1; o < 32; o <<= 1) {
            int u2 = __shfl_up_sync(0xffffffffu, v, o);
            if (lane >= o) v += u2;
        }
        if (lane < NWARP) iscn[lane] = v;
        if (lane == NWARP - 1) s_m = v;
    }
    __syncthreads();
    const int m = s_m;
    int idx = (wid ? iscn[wid - 1] : 0) + (incl - cnt);

    // ---- Phase A3: deterministic compacted scatter ----
    #pragma unroll
    for (int q = 0; q < MAXQ; ++q) {
        if (flags & (1u << q)) {
            fview[(idx >> 1) * 4 +     (idx & 1)] = rp[q];
            fview[(idx >> 1) * 4 + 2 + (idx & 1)] = rt[q];
            idx++;
        }
    }
    if (tid == 0 && (m & 1)) {         // zero-pad odd column
        fview[(m >> 1) * 4 +     1] = 0.0f;
        fview[(m >> 1) * 4 + 2 + 1] = 0.0f;
    }
    __syncthreads();

    // ---- Phase B: warp-panel triangle.
    //  Panel p: rows [128p, 128p+128), lane owns 4 rows, all lanes share k.
    //  Panel p covers column-pairs k in [64p, P):
    //    k in [64p, 64p+64)  -> diagonal 128x128 block, weight 1/2
    //    k in [64p+64, P)    -> off-diagonal rectangle, weight 1
    //  Work unit = one (panel, k). Units flattened; warps take even intervals.
    float v = 0.0f;
    if (m > 1) {
        const int P  = (m + 1) >> 1;            // column pairs (incl. pad)
        const int RP = (m + 127) >> 7;          // 128-row panels
        // Cpre(p) = p*P - 32*p*(p-1); W = Cpre(RP)
        const unsigned W = (unsigned)(RP * (P - 32 * (RP - 1)));
        const unsigned uw = (unsigned)(blockIdx.x * NWARP + wid);
        const unsigned w0 = (unsigned)((unsigned long long)uw * W / NWT);
        const unsigned w1 = (unsigned)((unsigned long long)(uw + 1) * W / NWT);

        if (w0 < w1) {
            // panel lookup: largest p with Cpre(p) <= w0 (float guess + fixup)
            int p;
            {
                float A = (float)(P + 32);
                float disc = fmaxf(A * A - 128.0f * (float)w0, 0.0f);
                p = (int)((A - sqrtf(disc)) * (1.0f / 64.0f));
                if (p < 0) p = 0;
                if (p > RP - 1) p = RP - 1;
                while (p + 1 <= RP - 1 &&
                       (p + 1) * (P - 32 * p) <= (int)w0) ++p;
                while (p > 0 && p * (P - 32 * (p - 1)) > (int)w0) --p;
            }

            unsigned w = w0;
            while (w < w1) {
                const int cs   = p * (P - 32 * (p - 1));   // Cpre(p)
                const int pend = cs + (P - 64 * p);

                // load this panel's 4 rows for this lane (once per panel)
                const int rbase = 64 * p + 2 * lane;
                ulonglong2 ra = cview[rbase];
                ulonglong2 rb = cview[rbase + 1];
                float q0, q1, q2, q3, u0, u1, u2, u3;
                UNPACKF2(q0, q1, ra.x); UNPACKF2(u0, u1, ra.y);
                UNPACKF2(q2, q3, rb.x); UNPACKF2(u2, u3, rb.y);
                uint64_t pi2[4], ti2[4];
                PACKF2(pi2[0], -q0, -q0); PACKF2(ti2[0], -u0, -u0);
                PACKF2(pi2[1], -q1, -q1); PACKF2(ti2[1], -u1, -u1);
                PACKF2(pi2[2], -q2, -q2); PACKF2(ti2[2], -u2, -u2);
                PACKF2(pi2[3], -q3, -q3); PACKF2(ti2[3], -u3, -u3);
                const int row0 = 128 * p + 4 * lane;

                const unsigned dlim = (unsigned)min(pend, cs + 64);
                #pragma unroll
                for (int seg = 0; seg < 2; ++seg) {
                    const unsigned send =
                        min(w1, seg == 0 ? dlim : (unsigned)pend);
                    if (w < send) {
                        int k  = 64 * p + (int)(w - (unsigned)cs);
                        const int kn = k + (int)(send - w);
                        uint64_t sx[4] = {0, 0, 0, 0}, sa[4] = {0, 0, 0, 0};
                        #pragma unroll 2
                        for (; k < kn; ++k) {
                            ulonglong2 va = cview[k];     // broadcast LDS.128
                            #pragma unroll
                            for (int r = 0; r < 4; ++r) {
                                uint64_t dp2, dt2, x2, a2;
                                ADDF2(dp2, pi2[r], va.x);
                                ADDF2(dt2, ti2[r], va.y);
                                MULF2(x2, dp2, dt2);
                                ADDF2(sx[r], sx[r], x2);
                                a2 = x2 & 0x7fffffff7fffffffULL;
                                ADDF2(sa[r], sa[r], a2);
                            }
                        }
                        // relu sum = (Sx + S|x|)/2; diag segment halved again
                        const float wt = (seg == 0) ? 0.25f : 0.5f;
                        #pragma unroll
                        for (int r = 0; r < 4; ++r) {
                            if (row0 + r < m) {
                                float xl, xh, al, ah;
                                UNPACKF2(xl, xh, sx[r]);
                                UNPACKF2(al, ah, sa[r]);
                                v += wt * ((xl + xh) + (al + ah));
                            }
                        }
                        w = send;
                    }
                }
                ++p;
            }
        }

        // pad-column correction: pad (0,0) added relu(p_i*t_i) per row,
        // at weight 1/2 for rows in the last panel (all-diag), 1 otherwise.
        if (m & 1) {
            const int i = blockIdx.x * NT + tid;
            if (i < m) {
                float pn = fview[(i >> 1) * 4 +     (i & 1)];   // -p_i
                float tn = fview[(i >> 1) * 4 + 2 + (i & 1)];   // -t_i
                float wi = (i >= 128 * ((m + 127) >> 7) - 128) ? 0.5f : 1.0f;
                v -= wi * fmaxf(pn * tn, 0.0f);
            }
        }
    }

    // ---- Phase C: block reduce -> fixed-point global (order-free) ----
    #pragma unroll
    for (int o = 16; o > 0; o >>= 1) v += __shfl_down_sync(0xffffffffu, v, o);
    if (lane == 0) red[wid] = v;
    __syncthreads();
    if (wid == 0) {
        float t = (lane < NWARP) ? red[lane] : 0.0f;
        #pragma unroll
        for (int o = 16; o > 0; o >>= 1) t += __shfl_down_sync(0xffffffffu, t, o);
        if (lane == 0) {
            long long q = llrint((double)t * 65536.0);
            atomicAdd(&g_acc, (unsigned long long)q);
            __threadfence();
            unsigned r = atomicAdd(&g_done, 1u);
            if (r == (unsigned)(gridDim.x - 1)) {
                long long total = (long long)g_acc;
                double Usum = (double)total / 65536.0;  // unordered-pair relu sum
                float res = 0.0f;
                if (m > 1)
                    res = (float)(Usum / (50.0 * (double)m * ((double)m - 1.0)));
                out[0] = res;
                g_acc = 0ULL;
                g_done = 0u;
            }
        }
    }
}

extern "C" void kernel_launch(void* const* d_in, const int* in_sizes, int n_in,
                              void* d_out, int out_size) {
    const float* pred = (const float*)d_in[0];
    const float* gt   = (const float*)d_in[1];
    const int* ft     = (const int*)d_in[2];
    const int* fm     = (const int*)d_in[3];
    float* out        = (float*)d_out;
    const int n = in_sizes[0];

    cudaFuncSetAttribute(cindex_kernel,
                         cudaFuncAttributeMaxDynamicSharedMemorySize, SMEM_BYTES);
    cindex_kernel<<<NB, NT, SMEM_BYTES>>>(pred, gt, ft, fm, out, n);
}